// round 1
// baseline (speedup 1.0000x reference)
#include <cuda_runtime.h>

// Problem constants (fixed by the dataset)
#define NA 250000
#define NB 500000
#define NG 50000
#define DD 64
#define EA 1000000
#define EG 500000

// Output layout (float offsets): [atom_ft | ft(NB x 320) | global_ft]
#define OFF_FT  (NA * DD)                 // 16,000,000
#define OFF_GL  (OFF_FT + NB * 320)       // 176,000,000

// ft row layout (floats): [bond(0:64) | mean_a(64:128) | max_a(128:192) | mean_g(192:256) | max_g(256:320)]

// Scratch: per-bond in-degree counts (device globals, no allocation)
__device__ int g_cnt_a[NB];
__device__ int g_cnt_g[NB];

__global__ void zero_cnt_kernel() {
    int i = blockIdx.x * blockDim.x + threadIdx.x;
    if (i < NB) { g_cnt_a[i] = 0; g_cnt_g[i] = 0; }
}

// One pass: copy atom_ft, global_ft, bond_ft into out; init sum cols to 0 and
// max cols to -inf, all with float4 stores.
__global__ void init_kernel(const float4* __restrict__ atom4,
                            const float4* __restrict__ bond4,
                            const float4* __restrict__ glob4,
                            float4* __restrict__ out4) {
    const int ATOM_F4 = NA * 16;   // 4,000,000
    const int GL_F4   = NG * 16;   //   800,000
    const int FT_F4   = NB * 80;   // 40,000,000

    long long i = (long long)blockIdx.x * blockDim.x + threadIdx.x;
    if (i < ATOM_F4) { out4[i] = atom4[i]; return; }
    i -= ATOM_F4;
    if (i < GL_F4) { out4[(OFF_GL / 4) + i] = glob4[i]; return; }
    i -= GL_F4;
    if (i >= FT_F4) return;

    int row  = (int)(i / 80);
    int part = (int)(i % 80);
    float4* dst = out4 + (OFF_FT / 4) + i;
    if (part < 16) {                       // bond_ft copy
        *dst = bond4[(long long)row * 16 + part];
        return;
    }
    float4 v;
    if (part < 32 || (part >= 48 && part < 64)) {
        v = make_float4(0.f, 0.f, 0.f, 0.f);            // mean accumulators
    } else {
        float ninf = __int_as_float(0xFF800000);        // max accumulators
        v = make_float4(ninf, ninf, ninf, ninf);
    }
    *dst = v;
}

// Ordered-float atomic max: signed max for non-negative, unsigned min for negative.
// Valid given init value -inf (0xFF800000).
__device__ __forceinline__ void atomic_max_float(float* addr, float v) {
    if (v >= 0.0f) {
        atomicMax((int*)addr, __float_as_int(v));
    } else {
        atomicMin((unsigned int*)addr, __float_as_uint(v));
    }
}

// 16 threads per edge; each thread owns one float4 (4 of the 64 features).
// Sum via float4 atomicAdd (vector RED, sm_90+), max via 4 scalar int-trick atomics.
template<int NEDGE, int COL_SUM, int COL_MAX, bool USE_A>
__global__ void edge_kernel(const float4* __restrict__ src_ft4,
                            const int*  __restrict__ e_src,
                            const int*  __restrict__ e_dst,
                            float*      __restrict__ out) {
    long long t = (long long)blockIdx.x * blockDim.x + threadIdx.x;
    int e    = (int)(t >> 4);
    int lane = (int)(t & 15);
    if (e >= NEDGE) return;

    int s = e_src[e];
    int d = e_dst[e];

    float4 v = src_ft4[(long long)s * 16 + lane];
    float* ftrow = out + OFF_FT + (long long)d * 320;

    atomicAdd((float4*)(ftrow + COL_SUM + lane * 4), v);

    float* mp = ftrow + COL_MAX + lane * 4;
    atomic_max_float(mp + 0, v.x);
    atomic_max_float(mp + 1, v.y);
    atomic_max_float(mp + 2, v.z);
    atomic_max_float(mp + 3, v.w);

    if (lane == 0) {
        int* cnt = USE_A ? g_cnt_a : g_cnt_g;
        atomicAdd(cnt + d, 1);
    }
}

// Divide sums by count (in place), zero max columns where count == 0.
// One thread per float4 of the mean/max regions (NB * 64 threads).
__global__ void finalize_kernel(float* __restrict__ out) {
    int i = blockIdx.x * blockDim.x + threadIdx.x;
    if (i >= NB * 64) return;
    int row  = i >> 6;
    int part = i & 63;
    float* ftrow = out + OFF_FT + (long long)row * 320;

    if (part < 16) {
        int c = g_cnt_a[row];
        float inv = 1.0f / (float)(c > 1 ? c : 1);
        float4* p = (float4*)(ftrow + 64) + part;
        float4 s = *p;
        s.x *= inv; s.y *= inv; s.z *= inv; s.w *= inv;
        *p = s;
    } else if (part < 32) {
        if (g_cnt_a[row] == 0) {
            float4* p = (float4*)(ftrow + 128) + (part - 16);
            *p = make_float4(0.f, 0.f, 0.f, 0.f);
        }
    } else if (part < 48) {
        int c = g_cnt_g[row];
        float inv = 1.0f / (float)(c > 1 ? c : 1);
        float4* p = (float4*)(ftrow + 192) + (part - 32);
        float4 s = *p;
        s.x *= inv; s.y *= inv; s.z *= inv; s.w *= inv;
        *p = s;
    } else {
        if (g_cnt_g[row] == 0) {
            float4* p = (float4*)(ftrow + 256) + (part - 48);
            *p = make_float4(0.f, 0.f, 0.f, 0.f);
        }
    }
}

extern "C" void kernel_launch(void* const* d_in, const int* in_sizes, int n_in,
                              void* d_out, int out_size) {
    const float4* atom4   = (const float4*)d_in[0];
    const float4* bond4   = (const float4*)d_in[1];
    const float4* glob4   = (const float4*)d_in[2];
    const int*    a2b_src = (const int*)d_in[3];
    const int*    a2b_dst = (const int*)d_in[4];
    const int*    g2b_src = (const int*)d_in[5];
    const int*    g2b_dst = (const int*)d_in[6];
    float* out = (float*)d_out;

    zero_cnt_kernel<<<(NB + 255) / 256, 256>>>();

    long long total_f4 = (long long)NA * 16 + (long long)NG * 16 + (long long)NB * 80;
    init_kernel<<<(int)((total_f4 + 255) / 256), 256>>>(atom4, bond4, glob4, (float4*)out);

    edge_kernel<EA, 64, 128, true><<<(EA * 16 + 255) / 256, 256>>>(atom4, a2b_src, a2b_dst, out);
    edge_kernel<EG, 192, 256, false><<<(EG * 16 + 255) / 256, 256>>>(glob4, g2b_src, g2b_dst, out);

    finalize_kernel<<<(NB * 64 + 255) / 256, 256>>>(out);
}

// round 2
// speedup vs baseline: 2.4200x; 2.4200x over previous
#include <cuda_runtime.h>

// Problem constants (fixed by the dataset)
#define NA 250000
#define NB 500000
#define NG 50000
#define DD 64
#define EA 1000000
#define EG 500000

// Output layout (float offsets): [atom_ft | ft(NB x 320) | global_ft]
#define OFF_FT  (NA * DD)                 // 16,000,000
#define OFF_GL  (OFF_FT + NB * 320)       // 176,000,000

// Per-destination edge bins (atomic bump allocation; degrees are ~Poisson(2)
// and ~Poisson(1), so these capacities are astronomically safe; clamped anyway).
#define CAP_A 48
#define CAP_G 32

__device__ int g_cnt_a[NB];
__device__ int g_cnt_g[NB];
__device__ int g_bin_a[(long long)NB * CAP_A];
__device__ int g_bin_g[(long long)NB * CAP_G];

__global__ void zero_cnt_kernel() {
    int i = blockIdx.x * blockDim.x + threadIdx.x;
    if (i < NB) { g_cnt_a[i] = 0; g_cnt_g[i] = 0; }
}

template<int NEDGE, int CAP, bool USE_A>
__global__ void scatter_kernel(const int* __restrict__ e_src,
                               const int* __restrict__ e_dst) {
    int e = blockIdx.x * blockDim.x + threadIdx.x;
    if (e >= NEDGE) return;
    int s = e_src[e];
    int d = e_dst[e];
    int* cnt = USE_A ? g_cnt_a : g_cnt_g;
    int* bin = USE_A ? g_bin_a : g_bin_g;
    int pos = atomicAdd(cnt + d, 1);
    if (pos < CAP) bin[(long long)d * CAP + pos] = s;
}

// Fused gather-reduce: 16 threads per bond row; thread `lane` owns features
// [lane*4, lane*4+4). Writes bond copy + mean_a + max_a + mean_g + max_g,
// each output float exactly once.
__global__ void reduce_kernel(const float4* __restrict__ bond4,
                              const float4* __restrict__ atom4,
                              const float4* __restrict__ glob4,
                              float4* __restrict__ out4) {
    long long t = (long long)blockIdx.x * blockDim.x + threadIdx.x;
    int row  = (int)(t >> 4);
    int lane = (int)(t & 15);
    if (row >= NB) return;

    float4* __restrict__ orow = out4 + (OFF_FT / 4) + (long long)row * 80;

    // bond_ft passthrough
    orow[lane] = bond4[(long long)row * 16 + lane];

    const float NINF = __int_as_float(0xFF800000);

    // ---- atom -> bond (mean, max) ----
    {
        int deg = g_cnt_a[row];
        if (deg > CAP_A) deg = CAP_A;
        const int* __restrict__ bin = g_bin_a + (long long)row * CAP_A;
        float4 s = make_float4(0.f, 0.f, 0.f, 0.f);
        float4 m = make_float4(NINF, NINF, NINF, NINF);
        for (int j = 0; j < deg; j++) {
            int src = __ldg(bin + j);
            float4 v = __ldg(atom4 + (long long)src * 16 + lane);
            s.x += v.x; s.y += v.y; s.z += v.z; s.w += v.w;
            m.x = fmaxf(m.x, v.x); m.y = fmaxf(m.y, v.y);
            m.z = fmaxf(m.z, v.z); m.w = fmaxf(m.w, v.w);
        }
        float inv = 1.0f / (float)(deg > 1 ? deg : 1);
        orow[16 + lane] = make_float4(s.x * inv, s.y * inv, s.z * inv, s.w * inv);
        orow[32 + lane] = deg ? m : make_float4(0.f, 0.f, 0.f, 0.f);
    }

    // ---- global -> bond (mean, max) ----
    {
        int deg = g_cnt_g[row];
        if (deg > CAP_G) deg = CAP_G;
        const int* __restrict__ bin = g_bin_g + (long long)row * CAP_G;
        float4 s = make_float4(0.f, 0.f, 0.f, 0.f);
        float4 m = make_float4(NINF, NINF, NINF, NINF);
        for (int j = 0; j < deg; j++) {
            int src = __ldg(bin + j);
            float4 v = __ldg(glob4 + (long long)src * 16 + lane);
            s.x += v.x; s.y += v.y; s.z += v.z; s.w += v.w;
            m.x = fmaxf(m.x, v.x); m.y = fmaxf(m.y, v.y);
            m.z = fmaxf(m.z, v.z); m.w = fmaxf(m.w, v.w);
        }
        float inv = 1.0f / (float)(deg > 1 ? deg : 1);
        orow[48 + lane] = make_float4(s.x * inv, s.y * inv, s.z * inv, s.w * inv);
        orow[64 + lane] = deg ? m : make_float4(0.f, 0.f, 0.f, 0.f);
    }
}

extern "C" void kernel_launch(void* const* d_in, const int* in_sizes, int n_in,
                              void* d_out, int out_size) {
    const float4* atom4   = (const float4*)d_in[0];
    const float4* bond4   = (const float4*)d_in[1];
    const float4* glob4   = (const float4*)d_in[2];
    const int*    a2b_src = (const int*)d_in[3];
    const int*    a2b_dst = (const int*)d_in[4];
    const int*    g2b_src = (const int*)d_in[5];
    const int*    g2b_dst = (const int*)d_in[6];
    float* out = (float*)d_out;

    // Passthrough copies (device-to-device async copies are capture-legal)
    cudaMemcpyAsync(out, atom4, (size_t)NA * DD * sizeof(float),
                    cudaMemcpyDeviceToDevice);
    cudaMemcpyAsync(out + OFF_GL, glob4, (size_t)NG * DD * sizeof(float),
                    cudaMemcpyDeviceToDevice);

    zero_cnt_kernel<<<(NB + 255) / 256, 256>>>();

    scatter_kernel<EA, CAP_A, true ><<<(EA + 255) / 256, 256>>>(a2b_src, a2b_dst);
    scatter_kernel<EG, CAP_G, false><<<(EG + 255) / 256, 256>>>(g2b_src, g2b_dst);

    long long threads = (long long)NB * 16;
    reduce_kernel<<<(int)((threads + 255) / 256), 256>>>(bond4, atom4, glob4,
                                                         (float4*)out);
}

// round 3
// speedup vs baseline: 2.8086x; 1.1606x over previous
#include <cuda_runtime.h>

// Problem constants (fixed by the dataset)
#define NA 250000
#define NB 500000
#define NG 50000
#define DD 64
#define EA 1000000
#define EG 500000

// Output layout (float offsets): [atom_ft | ft(NB x 320) | global_ft]
#define OFF_FT  (NA * DD)                 // 16,000,000
#define OFF_GL  (OFF_FT + NB * 320)       // 176,000,000

// Per-destination edge bins (atomic bump allocation). Degrees ~Poisson(2)/(1);
// capacities astronomically safe; clamped anyway.
#define CAP_A 48
#define CAP_G 32

__device__ int g_cnt_a[NB];
__device__ int g_cnt_g[NB];
__device__ int g_bin_a[(long long)NB * CAP_A];
__device__ int g_bin_g[(long long)NB * CAP_G];

__global__ void zero_cnt_kernel() {
    int i = blockIdx.x * blockDim.x + threadIdx.x;
    if (i < NB) { g_cnt_a[i] = 0; g_cnt_g[i] = 0; }
}

// Both edge sets in one launch.
__global__ void scatter_kernel(const int* __restrict__ a_src,
                               const int* __restrict__ a_dst,
                               const int* __restrict__ g_src,
                               const int* __restrict__ g_dst) {
    int e = blockIdx.x * blockDim.x + threadIdx.x;
    if (e < EA) {
        int s = a_src[e];
        int d = a_dst[e];
        int pos = atomicAdd(g_cnt_a + d, 1);
        if (pos < CAP_A) g_bin_a[(long long)d * CAP_A + pos] = s;
    } else {
        int eg = e - EA;
        if (eg < EG) {
            int s = g_src[eg];
            int d = g_dst[eg];
            int pos = atomicAdd(g_cnt_g + d, 1);
            if (pos < CAP_G) g_bin_g[(long long)d * CAP_G + pos] = s;
        }
    }
}

#define ACC(v)                                                     \
    do {                                                           \
        s.x += (v).x; s.y += (v).y; s.z += (v).z; s.w += (v).w;    \
        m.x = fmaxf(m.x, (v).x); m.y = fmaxf(m.y, (v).y);          \
        m.z = fmaxf(m.z, (v).z); m.w = fmaxf(m.w, (v).w);          \
    } while (0)

// Unrolled-by-4 gather-reduce for one (bin, table) pair.
// Indices clamped to deg-1 so all 4 feature loads are unconditional (MLP=4);
// accumulation is predicated on validity.
__device__ __forceinline__ void gather_reduce(const int* __restrict__ bin,
                                              const float4* __restrict__ tab,
                                              int deg, int lane,
                                              float4* __restrict__ o_mean,
                                              float4* __restrict__ o_max) {
    const float NINF = __int_as_float(0xFF800000);
    float4 s = make_float4(0.f, 0.f, 0.f, 0.f);
    float4 m = make_float4(NINF, NINF, NINF, NINF);

    #pragma unroll 1
    for (int j = 0; j < deg; j += 4) {
        int last = deg - 1;
        int i0 = __ldg(bin + j);
        int i1 = __ldg(bin + (j + 1 <= last ? j + 1 : last));
        int i2 = __ldg(bin + (j + 2 <= last ? j + 2 : last));
        int i3 = __ldg(bin + (j + 3 <= last ? j + 3 : last));
        float4 v0 = __ldg(tab + (long long)i0 * 16 + lane);
        float4 v1 = __ldg(tab + (long long)i1 * 16 + lane);
        float4 v2 = __ldg(tab + (long long)i2 * 16 + lane);
        float4 v3 = __ldg(tab + (long long)i3 * 16 + lane);
        ACC(v0);
        if (j + 1 < deg) ACC(v1);
        if (j + 2 < deg) ACC(v2);
        if (j + 3 < deg) ACC(v3);
    }
    float inv = 1.0f / (float)(deg > 1 ? deg : 1);
    __stcs(o_mean, make_float4(s.x * inv, s.y * inv, s.z * inv, s.w * inv));
    __stcs(o_max, deg ? m : make_float4(0.f, 0.f, 0.f, 0.f));
}

// Fused: passthrough copies (leading blocks) + per-bond gather-reduce.
// Copies use __ldg reads (pre-warm L2 with the gather tables) and __stcs
// streaming stores; reduce uses __ldcs for bond rows, __stcs for all output.
#define COPY_BLOCKS ((NA * 16 + NG * 16) / 256)   // 18750
__global__ void fused_kernel(const float4* __restrict__ bond4,
                             const float4* __restrict__ atom4,
                             const float4* __restrict__ glob4,
                             float4* __restrict__ out4) {
    int b = blockIdx.x;
    if (b < COPY_BLOCKS) {
        int i = b * 256 + threadIdx.x;
        if (i < NA * 16) {
            __stcs(out4 + i, __ldg(atom4 + i));
        } else {
            int j = i - NA * 16;
            __stcs(out4 + (OFF_GL / 4) + j, __ldg(glob4 + j));
        }
        return;
    }

    long long t = (long long)(b - COPY_BLOCKS) * 256 + threadIdx.x;
    int row  = (int)(t >> 4);
    int lane = (int)(t & 15);
    if (row >= NB) return;

    float4* __restrict__ orow = out4 + (OFF_FT / 4) + (long long)row * 80;

    // bond_ft passthrough (streaming both ways)
    __stcs(orow + lane, __ldcs(bond4 + (long long)row * 16 + lane));

    int deg_a = g_cnt_a[row]; if (deg_a > CAP_A) deg_a = CAP_A;
    gather_reduce(g_bin_a + (long long)row * CAP_A, atom4, deg_a, lane,
                  orow + 16 + lane, orow + 32 + lane);

    int deg_g = g_cnt_g[row]; if (deg_g > CAP_G) deg_g = CAP_G;
    gather_reduce(g_bin_g + (long long)row * CAP_G, glob4, deg_g, lane,
                  orow + 48 + lane, orow + 64 + lane);
}

extern "C" void kernel_launch(void* const* d_in, const int* in_sizes, int n_in,
                              void* d_out, int out_size) {
    const float4* atom4   = (const float4*)d_in[0];
    const float4* bond4   = (const float4*)d_in[1];
    const float4* glob4   = (const float4*)d_in[2];
    const int*    a2b_src = (const int*)d_in[3];
    const int*    a2b_dst = (const int*)d_in[4];
    const int*    g2b_src = (const int*)d_in[5];
    const int*    g2b_dst = (const int*)d_in[6];
    float* out = (float*)d_out;

    zero_cnt_kernel<<<(NB + 255) / 256, 256>>>();

    scatter_kernel<<<(EA + EG + 255) / 256, 256>>>(a2b_src, a2b_dst,
                                                   g2b_src, g2b_dst);

    int reduce_blocks = (int)(((long long)NB * 16) / 256);   // 31250
    fused_kernel<<<COPY_BLOCKS + reduce_blocks, 256>>>(bond4, atom4, glob4,
                                                       (float4*)out);
}